// round 13
// baseline (speedup 1.0000x reference)
#include <cuda_runtime.h>
#include <math.h>
#include <stdint.h>

#define BB   16
#define CC   256
#define TT   1024
#define LE   32
#define CTX  48
#define CHK  16
#define WL   64
#define NH   8
#define DH   32
#define FFD  1024
#define NL   4
#define TEXT (CTX + TT)     /* 1072 */
#define EPSL 1e-5f

// ---------------- device scratch (sanctioned: __device__ globals, no allocs) -----
__device__ __align__(16) float g_actA[(size_t)BB * TT * CC];
__device__ __align__(16) float g_actB[(size_t)BB * TT * CC];
__device__ __align__(16) float g_ext [(size_t)BB * TEXT * CC];
__device__ __align__(16) float g_qkv [(size_t)BB * TEXT * 768];
__device__ __align__(16) float g_attn[(size_t)BB * TT * CC];
__device__ __align__(16) float g_x1  [(size_t)BB * TT * CC];
__device__ __align__(16) float g_h   [(size_t)BB * TT * FFD];
// tf32-rounded weights: wq | wo | w1 | w2
#define WQ_OFF 0
#define WO_OFF ((size_t)NL * 768 * CC)
#define W1_OFF (WO_OFF + (size_t)NL * CC * CC)
#define W2_OFF (W1_OFF + (size_t)NL * FFD * CC)
#define WTS_TOTAL (W2_OFF + (size_t)NL * CC * FFD)
__device__ __align__(16) float g_wts[WTS_TOTAL];

// ---------------- tf32 helpers --------------------------------------------------
__device__ __forceinline__ float to_tf32(float x) {
    uint32_t r;
    asm("cvt.rna.tf32.f32 %0, %1;" : "=r"(r) : "f"(x));
    return __uint_as_float(r);
}

// single kernel converting all four weight tensors into g_wts
__global__ void cvt_all_kernel(const float* __restrict__ Wqkv,
                               const float* __restrict__ Wo,
                               const float* __restrict__ W1,
                               const float* __restrict__ W2,
                               float* __restrict__ wts)
{
    size_t i = (size_t)blockIdx.x * blockDim.x + threadIdx.x;
    float v;
    if (i < WO_OFF)        v = Wqkv[i];
    else if (i < W1_OFF)   v = Wo[i - WO_OFF];
    else if (i < W2_OFF)   v = W1[i - W1_OFF];
    else                   v = W2[i - W2_OFF];
    wts[i] = to_tf32(v);
}

// ---------------- depthwise causal conv -----------------------------------------
__global__ void conv_kernel(const float* __restrict__ x,
                            const float* __restrict__ emb,
                            float* __restrict__ out)
{
    int c = blockIdx.x, b = blockIdx.y;
    __shared__ float xs[TT];
    __shared__ float f[LE];
    const float* xr = x + ((size_t)b * CC + c) * TT;
    for (int t = threadIdx.x; t < TT; t += blockDim.x) xs[t] = xr[t];
    if (threadIdx.x < LE) {
        int l = threadIdx.x;
        float e0 = emb[(((size_t)b * 2 + 0) * CC + c) * LE + l];
        float e1 = emb[(((size_t)b * 2 + 1) * CC + c) * LE + l];
        f[l] = 0.5f * (e0 + e1);
    }
    __syncthreads();
    for (int t = threadIdx.x; t < TT; t += blockDim.x) {
        float acc = 0.f;
        #pragma unroll
        for (int l = 0; l < LE; l++) {
            int src = t - (LE - 1) + l;
            if (src >= 0) acc = fmaf(f[l], xs[src], acc);
        }
        out[((size_t)b * TT + t) * CC + c] = acc;
    }
}

// ---------------- build ext (tf32-rounded) + ctx snapshot (raw) in one pass -----
__global__ void build_ext_snap(const float* __restrict__ ctx, const float* __restrict__ act,
                               float* __restrict__ ext, float* __restrict__ out_ctx,
                               int layer)
{
    size_t idx = (size_t)blockIdx.x * blockDim.x + threadIdx.x;  // B*TEXT*C
    int c = (int)(idx & (CC - 1));
    size_t row = idx >> 8;
    int te = (int)(row % TEXT);
    int b  = (int)(row / TEXT);
    float v;
    if (te < CTX) {
        v = ctx[(((size_t)b * NL + layer) * CTX + te) * CC + c];
    } else {
        v = act[((size_t)b * TT + (te - CTX)) * CC + c];
        if (te >= TEXT - CTX) {   // last CTX extended rows = snapshot (unrounded)
            int j = te - (TEXT - CTX);
            out_ctx[(((size_t)b * NL + layer) * CTX + j) * CC + c] = v;
        }
    }
    ext[idx] = to_tf32(v);
}

// ---------------- tf32 tensor-core GEMM -----------------------------------------
// out[m][n] = sum_k A[m][k]*W[n][k] + bias[n] (+res)(relu).
// 128x128x32 CTA tile, 256 threads = 8 warps (4x2), 32x64 warp tiles, 2 CTAs/SM.
// 3-stage cp.async pipeline, ONE __syncthreads per k-iter.
// Stride-32 smem rows with 16B-chunk XOR swizzle (chunk ^= (row&3)<<1) and
// commutative-k slot remap: mma group g uses phys k {8g+2lk, 8g+2lk+1} for
// slots (lk, lk+4): per-group fragments are single float2 (LDS.64).
#define NSTAGE 3
#define STAGE_F (128 * 32 * 2)              /* floats per stage (A+B) = 8192 */
#define GEMM_SMEM (NSTAGE * STAGE_F * 4)    /* bytes: 98304 */

__device__ __forceinline__ void cp16(uint32_t dst, const float* src) {
    asm volatile("cp.async.cg.shared.global [%0], [%1], 16;" :: "r"(dst), "l"(src));
}

template<int RELU, int HASRES>
__global__ void __launch_bounds__(256, 2) mma_gemm(
    const float* __restrict__ A, const float* __restrict__ W,
    const float* __restrict__ bias, const float* __restrict__ res,
    float* __restrict__ out, int M, int N, int K)
{
    extern __shared__ float sm[];
    const int tid = threadIdx.x;
    const int n0 = blockIdx.x * 128;
    const int m0 = blockIdx.y * 128;
    const int warp = tid >> 5, lane = tid & 31;
    const int wm = (warp & 3) * 32;
    const int wn = (warp >> 2) * 64;
    const int lr = lane >> 2;       // 0..7
    const int lk = lane & 3;        // 0..3
    const int s3 = lr & 3;          // row&3 for all fragment rows this thread touches

    // global->smem mapping: thread copies 4 x 16B for A and for B per stage
    const int arow = tid >> 3;      // 0..31
    const int akc  = tid & 7;       // logical 16B chunk within 32-float k-row
    const int cph  = akc ^ ((arow & 3) << 1);   // swizzled chunk (rows step by 32)
    const float* Ag = A + (size_t)(m0 + arow) * K + akc * 4;
    const float* Wg = W + (size_t)(n0 + arow) * K + akc * 4;

    float acc[2][8][4];
    #pragma unroll
    for (int i = 0; i < 2; i++)
        #pragma unroll
        for (int j = 0; j < 8; j++)
            #pragma unroll
            for (int q = 0; q < 4; q++) acc[i][j][q] = 0.f;

    uint32_t smem_base = (uint32_t)__cvta_generic_to_shared(sm);

    // ---- load a stage (swizzled stride-32 layout) ----
    #define LOAD_STAGE(s, k0)                                                 \
    do {                                                                      \
        uint32_t dA = smem_base + (uint32_t)((s) * STAGE_F) * 4;              \
        uint32_t dB = dA + (uint32_t)(128 * 32) * 4;                          \
        _Pragma("unroll")                                                     \
        for (int c = 0; c < 4; c++) {                                         \
            int r = arow + 32 * c;                                            \
            cp16(dA + (uint32_t)(r * 32 + 4 * cph) * 4,                       \
                 Ag + (size_t)(32 * c) * K + (k0));                           \
            cp16(dB + (uint32_t)(r * 32 + 4 * cph) * 4,                       \
                 Wg + (size_t)(32 * c) * K + (k0));                           \
        }                                                                     \
    } while (0)

    const int niter = K >> 5;
    LOAD_STAGE(0, 0);
    asm volatile("cp.async.commit_group;");
    LOAD_STAGE(1, 32);
    asm volatile("cp.async.commit_group;");

    int rs = 0;                              // stage being read this iter
    for (int it = 0; it < niter; it++) {
        if (it + 1 < niter)
            asm volatile("cp.async.wait_group 1;");
        else
            asm volatile("cp.async.wait_group 0;");
        __syncthreads();

        // prefetch stage it+2 into buffer consumed at iter it-1 (all readers
        // passed the barrier above)
        if (it + 2 < niter) {
            int ps = rs + 2; if (ps >= NSTAGE) ps -= NSTAGE;
            LOAD_STAGE(ps, (it + 2) * 32);
            asm volatile("cp.async.commit_group;");
        }

        const float* As = sm + rs * STAGE_F;
        const float* Bs = As + 128 * 32;
        const float* a0p = As + (wm + lr) * 32 + 2 * lk;
        const float* b0p = Bs + (wn + lr) * 32 + 2 * lk;

        #pragma unroll
        for (int g = 0; g < 4; g++) {
            const int blk = (g ^ s3) << 3;   // swizzled 8-word block for this group
            float2 fa[2][2], fb[8];
            #pragma unroll
            for (int mt = 0; mt < 2; mt++) {
                fa[mt][0] = *(const float2*)(a0p + (mt * 16) * 32 + blk);
                fa[mt][1] = *(const float2*)(a0p + (mt * 16 + 8) * 32 + blk);
            }
            #pragma unroll
            for (int nt = 0; nt < 8; nt++)
                fb[nt] = *(const float2*)(b0p + (nt * 8) * 32 + blk);

            #pragma unroll
            for (int mt = 0; mt < 2; mt++) {
                uint32_t a0 = __float_as_uint(fa[mt][0].x);
                uint32_t a1 = __float_as_uint(fa[mt][1].x);
                uint32_t a2 = __float_as_uint(fa[mt][0].y);
                uint32_t a3 = __float_as_uint(fa[mt][1].y);
                #pragma unroll
                for (int nt = 0; nt < 8; nt++) {
                    uint32_t b0 = __float_as_uint(fb[nt].x);
                    uint32_t b1 = __float_as_uint(fb[nt].y);
                    asm volatile(
                        "mma.sync.aligned.m16n8k8.row.col.f32.tf32.tf32.f32 "
                        "{%0,%1,%2,%3}, {%4,%5,%6,%7}, {%8,%9}, {%0,%1,%2,%3};"
                        : "+f"(acc[mt][nt][0]), "+f"(acc[mt][nt][1]),
                          "+f"(acc[mt][nt][2]), "+f"(acc[mt][nt][3])
                        : "r"(a0), "r"(a1), "r"(a2), "r"(a3),
                          "r"(b0), "r"(b1));
                }
            }
        }
        rs++; if (rs >= NSTAGE) rs = 0;
    }

    // ---- epilogue ----
    #pragma unroll
    for (int mt = 0; mt < 2; mt++) {
        const int r0 = m0 + wm + mt * 16 + lr;
        const int r1 = r0 + 8;
        #pragma unroll
        for (int nt = 0; nt < 8; nt++) {
            const int cbase = n0 + wn + nt * 8 + lk * 2;
            float2 bv = *(const float2*)(bias + cbase);
            float o0 = acc[mt][nt][0] + bv.x;
            float o1 = acc[mt][nt][1] + bv.y;
            float o2 = acc[mt][nt][2] + bv.x;
            float o3 = acc[mt][nt][3] + bv.y;
            if (HASRES) {
                float2 rv0 = *(const float2*)(res + (size_t)r0 * N + cbase);
                float2 rv1 = *(const float2*)(res + (size_t)r1 * N + cbase);
                o0 += rv0.x; o1 += rv0.y; o2 += rv1.x; o3 += rv1.y;
            }
            if (RELU) {   // relu output feeds next GEMM as A: round to tf32
                o0 = to_tf32(fmaxf(o0, 0.f));
                o1 = to_tf32(fmaxf(o1, 0.f));
                o2 = to_tf32(fmaxf(o2, 0.f));
                o3 = to_tf32(fmaxf(o3, 0.f));
            }
            float2 s0 = {o0, o1}, s1 = {o2, o3};
            *(float2*)(out + (size_t)r0 * N + cbase) = s0;
            *(float2*)(out + (size_t)r1 * N + cbase) = s1;
        }
    }
    #undef LOAD_STAGE
}

// ---------------- windowed attention, 4 heads per block (2 blocks per window) ---
// grid (WL, BB, 2); z selects head-half (cols z*128 .. z*128+127 of Q/K/V).
#define AKSTR 129
#define ATTN_SMEM ((16*128 + 64*AKSTR + 4*16*64) * 4)   /* 57600 B */
__global__ void __launch_bounds__(128) attn_kernel(const float* __restrict__ qkv,
                                                   float* __restrict__ aout)
{
    extern __shared__ float sm[];
    float* sQ = sm;                       // [16][128]
    float* sK = sm + 16 * 128;            // [64][AKSTR]
    float* sP = sK + 64 * AKSTR;          // [4][16][64]
    int w = blockIdx.x, b = blockIdx.y, z = blockIdx.z;
    int tid = threadIdx.x;
    size_t base = ((size_t)b * TEXT + (size_t)w * CHK) * 768;
    const int colq = z * 128;

    for (int idx = tid; idx < 16 * 128; idx += 128) {
        int r = idx >> 7, c = idx & 127;
        sQ[idx] = qkv[base + (size_t)(CTX + r) * 768 + colq + c];
    }
    for (int idx = tid; idx < 64 * 128; idx += 128) {
        int j = idx >> 7, c = idx & 127;
        sK[j * AKSTR + c] = qkv[base + (size_t)j * 768 + 256 + colq + c];
    }
    __syncthreads();

    int hl = tid >> 5, lane = tid & 31;   // hl 0..3
    const float scale = 0.17677669529663687f;  // 1/sqrt(32)
    for (int r = 0; r < CHK; r++) {
        float s0 = 0.f, s1 = 0.f;
        const float* qrow = sQ + r * 128 + hl * 32;
        const float* k0 = sK + lane * AKSTR + hl * 32;
        const float* k1 = sK + (lane + 32) * AKSTR + hl * 32;
        #pragma unroll
        for (int d = 0; d < DH; d++) {
            float q = qrow[d];
            s0 = fmaf(q, k0[d], s0);
            s1 = fmaf(q, k1[d], s1);
        }
        s0 *= scale; s1 *= scale;
        float mx = fmaxf(s0, s1);
        #pragma unroll
        for (int o = 16; o > 0; o >>= 1)
            mx = fmaxf(mx, __shfl_xor_sync(0xffffffffu, mx, o));
        float e0 = __expf(s0 - mx), e1 = __expf(s1 - mx);
        float sum = e0 + e1;
        #pragma unroll
        for (int o = 16; o > 0; o >>= 1)
            sum += __shfl_xor_sync(0xffffffffu, sum, o);
        float inv = __frcp_rn(sum);
        sP[(hl * CHK + r) * 64 + lane]      = e0 * inv;
        sP[(hl * CHK + r) * 64 + lane + 32] = e1 * inv;
    }
    // AV: lane owns dim d = lane of its head's 32-dim slice
    float acc[CHK];
    #pragma unroll
    for (int r = 0; r < CHK; r++) acc[r] = 0.f;
    for (int j = 0; j < WL; j++) {
        float v = qkv[base + (size_t)j * 768 + 512 + colq + hl * 32 + lane];
        #pragma unroll
        for (int r = 0; r < CHK; r++)
            acc[r] = fmaf(sP[(hl * CHK + r) * 64 + j], v, acc[r]);
    }
    size_t obase = ((size_t)b * TT + (size_t)w * CHK) * CC + colq + hl * 32 + lane;
    #pragma unroll
    for (int r = 0; r < CHK; r++) aout[obase + (size_t)r * CC] = to_tf32(acc[r]);
}

// ---------------- layernorm (ROUND=1 -> output tf32-rounded for next GEMM) ------
template<int ROUND>
__global__ void ln_kernel(const float* in, const float* __restrict__ g,
                          const float* __restrict__ bt, float* outp)
{
    int row = blockIdx.x * 8 + (threadIdx.x >> 5);
    int lane = threadIdx.x & 31;
    const float* r = in + (size_t)row * CC;
    float v[8];
    float sum = 0.f;
    #pragma unroll
    for (int i = 0; i < 8; i++) { v[i] = r[lane + 32 * i]; sum += v[i]; }
    #pragma unroll
    for (int o = 16; o > 0; o >>= 1) sum += __shfl_xor_sync(0xffffffffu, sum, o);
    float mu = sum * (1.f / 256.f);
    float vs = 0.f;
    #pragma unroll
    for (int i = 0; i < 8; i++) { float d = v[i] - mu; vs = fmaf(d, d, vs); }
    #pragma unroll
    for (int o = 16; o > 0; o >>= 1) vs += __shfl_xor_sync(0xffffffffu, vs, o);
    float rs = rsqrtf(vs * (1.f / 256.f) + EPSL);
    float* o = outp + (size_t)row * CC;
    #pragma unroll
    for (int i = 0; i < 8; i++) {
        int c = lane + 32 * i;
        float y = (v[i] - mu) * rs * g[c] + bt[c];
        o[c] = ROUND ? to_tf32(y) : y;
    }
}

// ---------------- final transpose (B,T,C) -> (B,C,T) ----------------------------
__global__ void transpose_out(const float* __restrict__ act, float* __restrict__ out)
{
    __shared__ float tile[32][33];
    int b = blockIdx.z;
    int t0 = blockIdx.x * 32, c0 = blockIdx.y * 32;
    int tx = threadIdx.x & 31, ty = threadIdx.x >> 5;
    for (int i = ty; i < 32; i += 8)
        tile[i][tx] = act[((size_t)b * TT + t0 + i) * CC + c0 + tx];
    __syncthreads();
    for (int i = ty; i < 32; i += 8)
        out[((size_t)b * CC + c0 + i) * TT + t0 + tx] = tile[tx][i];
}

// ---------------- orchestration -------------------------------------------------
extern "C" void kernel_launch(void* const* d_in, const int* in_sizes, int n_in,
                              void* d_out, int out_size)
{
    (void)in_sizes; (void)n_in; (void)out_size;
    const float* x    = (const float*)d_in[0];
    const float* emb  = (const float*)d_in[1];
    const float* ctx  = (const float*)d_in[2];
    const float* Wqkv = (const float*)d_in[3];
    const float* bqkv = (const float*)d_in[4];
    const float* Wo   = (const float*)d_in[5];
    const float* bo   = (const float*)d_in[6];
    const float* W1   = (const float*)d_in[7];
    const float* b1   = (const float*)d_in[8];
    const float* W2   = (const float*)d_in[9];
    const float* b2   = (const float*)d_in[10];
    const float* ln1g = (const float*)d_in[11];
    const float* ln1b = (const float*)d_in[12];
    const float* ln3g = (const float*)d_in[13];
    const float* ln3b = (const float*)d_in[14];
    float* out     = (float*)d_out;
    float* out_ctx = out + (size_t)BB * CC * TT;

    float *actA, *actB, *ext, *qkv, *attn, *x1, *h, *wts;
    cudaGetSymbolAddress((void**)&actA, g_actA);
    cudaGetSymbolAddress((void**)&actB, g_actB);
    cudaGetSymbolAddress((void**)&ext,  g_ext);
    cudaGetSymbolAddress((void**)&qkv,  g_qkv);
    cudaGetSymbolAddress((void**)&attn, g_attn);
    cudaGetSymbolAddress((void**)&x1,   g_x1);
    cudaGetSymbolAddress((void**)&h,    g_h);
    cudaGetSymbolAddress((void**)&wts,  g_wts);
    float* wq = wts + WQ_OFF;
    float* wo = wts + WO_OFF;
    float* w1 = wts + W1_OFF;
    float* w2 = wts + W2_OFF;

    cudaFuncSetAttribute(attn_kernel, cudaFuncAttributeMaxDynamicSharedMemorySize,
                         ATTN_SMEM);
    cudaFuncSetAttribute(mma_gemm<0,0>, cudaFuncAttributeMaxDynamicSharedMemorySize,
                         GEMM_SMEM);
    cudaFuncSetAttribute(mma_gemm<0,1>, cudaFuncAttributeMaxDynamicSharedMemorySize,
                         GEMM_SMEM);
    cudaFuncSetAttribute(mma_gemm<1,0>, cudaFuncAttributeMaxDynamicSharedMemorySize,
                         GEMM_SMEM);

    // weight conversion to tf32 (one launch)
    cvt_all_kernel<<<(int)(WTS_TOTAL / 256), 256>>>(Wqkv, Wo, W1, W2, wts);

    conv_kernel<<<dim3(CC, BB), 256>>>(x, emb, actA);

    float* cur = actA;
    float* nxt = actB;
    const int Mq = BB * TT;          // 16384
    const int Me = BB * TEXT;        // 17152
    for (int L = 0; L < NL; L++) {
        build_ext_snap<<<(BB * TEXT * CC) / 256, 256>>>(ctx, cur, ext, out_ctx, L);
        // fused QKV projection over extended tokens (tf32 tensor core)
        mma_gemm<0, 0><<<dim3(768 / 128, Me / 128), 256, GEMM_SMEM>>>(
            ext, wq + (size_t)L * 768 * CC, bqkv + (size_t)L * 768,
            (const float*)0, qkv, Me, 768, CC);
        attn_kernel<<<dim3(WL, BB, 2), 128, ATTN_SMEM>>>(qkv, attn);
        // Wo + residual(cur) -> x1, then LN1 in place (rounded for FF1)
        mma_gemm<0, 1><<<dim3(CC / 128, Mq / 128), 256, GEMM_SMEM>>>(
            attn, wo + (size_t)L * CC * CC, bo + (size_t)L * CC,
            cur, x1, Mq, CC, CC);
        ln_kernel<1><<<Mq / 8, 256>>>(x1, ln1g + (size_t)L * CC, ln1b + (size_t)L * CC, x1);
        // FF1 (relu, output rounded)
        mma_gemm<1, 0><<<dim3(FFD / 128, Mq / 128), 256, GEMM_SMEM>>>(
            x1, w1 + (size_t)L * FFD * CC, b1 + (size_t)L * FFD,
            (const float*)0, h, Mq, FFD, CC);
        // FF2 + residual(x1), then LN3 in place (no rounding: final precision)
        mma_gemm<0, 1><<<dim3(CC / 128, Mq / 128), 256, GEMM_SMEM>>>(
            h, w2 + (size_t)L * CC * FFD, b2 + (size_t)L * CC,
            x1, nxt, Mq, CC, FFD);
        ln_kernel<0><<<Mq / 8, 256>>>(nxt, ln3g + (size_t)L * CC, ln3b + (size_t)L * CC, nxt);
        float* tmp = cur; cur = nxt; nxt = tmp;
    }

    transpose_out<<<dim3(TT / 32, CC / 32, BB), 256>>>(cur, out);
}

// round 16
// speedup vs baseline: 1.2241x; 1.2241x over previous
#include <cuda_runtime.h>
#include <cuda_fp16.h>
#include <math.h>
#include <stdint.h>

#define BB   16
#define CC   256
#define TT   1024
#define LE   32
#define CTX  48
#define CHK  16
#define WL   64
#define NH   8
#define DH   32
#define FFD  1024
#define NL   4
#define TEXT (CTX + TT)     /* 1072 */
#define EPSL 1e-5f

// ---------------- device scratch (sanctioned: __device__ globals, no allocs) -----
__device__ __align__(16) float  g_actA[(size_t)BB * TT * CC];
__device__ __align__(16) float  g_actB[(size_t)BB * TT * CC];
__device__ __align__(16) __half g_ext [(size_t)BB * TEXT * CC];
__device__ __align__(16) float  g_qkv [(size_t)BB * TEXT * 768];
__device__ __align__(16) __half g_attn[(size_t)BB * TT * CC];
__device__ __align__(16) float  g_x1  [(size_t)BB * TT * CC];
__device__ __align__(16) __half g_x1h [(size_t)BB * TT * CC];
__device__ __align__(16) __half g_h   [(size_t)BB * TT * FFD];
// fp16 weights: wq | wo | w1 | w2
#define WQ_OFF 0
#define WO_OFF ((size_t)NL * 768 * CC)
#define W1_OFF (WO_OFF + (size_t)NL * CC * CC)
#define W2_OFF (W1_OFF + (size_t)NL * FFD * CC)
#define WTS_TOTAL (W2_OFF + (size_t)NL * CC * FFD)
__device__ __align__(16) __half g_wts[WTS_TOTAL];

// ---------------- converters -----------------------------------------------------
__global__ void cvt_all_kernel(const float* __restrict__ Wqkv,
                               const float* __restrict__ Wo,
                               const float* __restrict__ W1,
                               const float* __restrict__ W2,
                               __half* __restrict__ wts)
{
    size_t i = (size_t)blockIdx.x * blockDim.x + threadIdx.x;
    float v;
    if (i < WO_OFF)        v = Wqkv[i];
    else if (i < W1_OFF)   v = Wo[i - WO_OFF];
    else if (i < W2_OFF)   v = W1[i - W1_OFF];
    else                   v = W2[i - W2_OFF];
    wts[i] = __float2half_rn(v);
}

// ---------------- depthwise causal conv -----------------------------------------
__global__ void conv_kernel(const float* __restrict__ x,
                            const float* __restrict__ emb,
                            float* __restrict__ out)
{
    int c = blockIdx.x, b = blockIdx.y;
    __shared__ float xs[TT];
    __shared__ float f[LE];
    const float* xr = x + ((size_t)b * CC + c) * TT;
    for (int t = threadIdx.x; t < TT; t += blockDim.x) xs[t] = xr[t];
    if (threadIdx.x < LE) {
        int l = threadIdx.x;
        float e0 = emb[(((size_t)b * 2 + 0) * CC + c) * LE + l];
        float e1 = emb[(((size_t)b * 2 + 1) * CC + c) * LE + l];
        f[l] = 0.5f * (e0 + e1);
    }
    __syncthreads();
    for (int t = threadIdx.x; t < TT; t += blockDim.x) {
        float acc = 0.f;
        #pragma unroll
        for (int l = 0; l < LE; l++) {
            int src = t - (LE - 1) + l;
            if (src >= 0) acc = fmaf(f[l], xs[src], acc);
        }
        out[((size_t)b * TT + t) * CC + c] = acc;
    }
}

// ---------------- build ext (fp16) + ctx snapshot (raw f32) in one pass ---------
__global__ void build_ext_snap(const float* __restrict__ ctx, const float* __restrict__ act,
                               __half* __restrict__ ext, float* __restrict__ out_ctx,
                               int layer)
{
    size_t idx = (size_t)blockIdx.x * blockDim.x + threadIdx.x;  // B*TEXT*C
    int c = (int)(idx & (CC - 1));
    size_t row = idx >> 8;
    int te = (int)(row % TEXT);
    int b  = (int)(row / TEXT);
    float v;
    if (te < CTX) {
        v = ctx[(((size_t)b * NL + layer) * CTX + te) * CC + c];
    } else {
        v = act[((size_t)b * TT + (te - CTX)) * CC + c];
        if (te >= TEXT - CTX) {
            int j = te - (TEXT - CTX);
            out_ctx[(((size_t)b * NL + layer) * CTX + j) * CC + c] = v;
        }
    }
    ext[idx] = __float2half_rn(v);
}

// ---------------- fp16 tensor-core GEMM (mma.sync m16n8k16) ---------------------
// out[m][n] = sum_k A[m][k]*W[n][k] + bias[n] (+res f32)(relu -> half out).
// 128x128x32 CTA tile, 256 threads = 8 warps (4x2), 32x64 warp tiles, 2 CTAs/SM.
// 2-stage cp.async. Smem rows = 32 halves (64B), 16B-chunk swizzle c ^= row&3.
// Commutative-k remap: mma (step s, pair p) consumes phys k = 8t+4s+2p+{0,1},
// so a thread's k32 fragment per row is ONE 16B chunk (LDS.128), conflict-free.
#define STAGE_B (128 * 64 * 2)          /* bytes per stage (A+B) = 16384 */
#define GEMM_SMEM (2 * STAGE_B)         /* 32768 */

__device__ __forceinline__ void cp16(uint32_t dst, const void* src) {
    asm volatile("cp.async.cg.shared.global [%0], [%1], 16;" :: "r"(dst), "l"(src));
}
__device__ __forceinline__ void mma16816(float* c, uint32_t a0, uint32_t a1,
                                         uint32_t a2, uint32_t a3,
                                         uint32_t b0, uint32_t b1)
{
    asm volatile(
        "mma.sync.aligned.m16n8k16.row.col.f32.f16.f16.f32 "
        "{%0,%1,%2,%3}, {%4,%5,%6,%7}, {%8,%9}, {%0,%1,%2,%3};"
        : "+f"(c[0]), "+f"(c[1]), "+f"(c[2]), "+f"(c[3])
        : "r"(a0), "r"(a1), "r"(a2), "r"(a3), "r"(b0), "r"(b1));
}

template<int RELU, int HASRES>
__global__ void __launch_bounds__(256, 2) mma_gemm(
    const __half* __restrict__ A, const __half* __restrict__ W,
    const float* __restrict__ bias, const float* __restrict__ res,
    void* __restrict__ outv, int M, int N, int K)
{
    extern __shared__ char smc[];
    const int tid = threadIdx.x;
    const int n0 = blockIdx.x * 128;
    const int m0 = blockIdx.y * 128;
    const int warp = tid >> 5, lane = tid & 31;
    const int wm = (warp & 3) * 32;
    const int wn = (warp >> 2) * 64;
    const int lr = lane >> 2;       // group 0..7
    const int lk = lane & 3;        // thread-in-group
    const int fco = 16 * (lk ^ (lr & 3));   // fragment 16B chunk offset in row

    // loader: thread handles rows (arow, arow+64) of A and B, 16B chunk ac
    const int arow = tid >> 2;      // 0..63
    const int ac   = tid & 3;       // logical chunk (k offset 8*ac halves)
    const int aph  = 16 * (ac ^ (arow & 3));   // phys byte offset in 64B row
    const __half* Ag = A + (size_t)(m0 + arow) * K + ac * 8;
    const __half* Wg = W + (size_t)(n0 + arow) * K + ac * 8;

    float acc[2][8][4];
    #pragma unroll
    for (int i = 0; i < 2; i++)
        #pragma unroll
        for (int j = 0; j < 8; j++)
            #pragma unroll
            for (int q = 0; q < 4; q++) acc[i][j][q] = 0.f;

    uint32_t smem_base = (uint32_t)__cvta_generic_to_shared(smc);

    #define LOAD_STAGE(s, k0)                                                 \
    do {                                                                      \
        uint32_t dA = smem_base + (uint32_t)((s) * STAGE_B);                  \
        uint32_t dB = dA + 128 * 64;                                          \
        _Pragma("unroll")                                                     \
        for (int c2 = 0; c2 < 2; c2++) {                                      \
            int r = arow + 64 * c2;                                           \
            cp16(dA + (uint32_t)(r * 64) + aph,                               \
                 Ag + (size_t)(64 * c2) * K + (k0));                          \
            cp16(dB + (uint32_t)(r * 64) + aph,                               \
                 Wg + (size_t)(64 * c2) * K + (k0));                          \
        }                                                                     \
    } while (0)

    const int niter = K >> 5;
    LOAD_STAGE(0, 0);
    asm volatile("cp.async.commit_group;");

    for (int it = 0; it < niter; it++) {
        if (it + 1 < niter) {
            LOAD_STAGE((it + 1) & 1, (it + 1) * 32);
            asm volatile("cp.async.commit_group;");
            asm volatile("cp.async.wait_group 1;");
        } else {
            asm volatile("cp.async.wait_group 0;");
        }
        __syncthreads();

        const char* As = smc + (it & 1) * STAGE_B;
        const char* Bs = As + 128 * 64;

        // A fragments: [mt][rowgroup g / g+8], 16B each covering whole k32
        uint4 va[2][2];
        #pragma unroll
        for (int mt = 0; mt < 2; mt++) {
            va[mt][0] = *(const uint4*)(As + (wm + mt * 16 + lr) * 64 + fco);
            va[mt][1] = *(const uint4*)(As + (wm + mt * 16 + 8 + lr) * 64 + fco);
        }
        #pragma unroll
        for (int nt = 0; nt < 8; nt++) {
            uint4 vb = *(const uint4*)(Bs + (wn + nt * 8 + lr) * 64 + fco);
            // step 0: pairs (.x = p0, .y = p1)
            #pragma unroll
            for (int mt = 0; mt < 2; mt++)
                mma16816(acc[mt][nt], va[mt][0].x, va[mt][1].x,
                         va[mt][0].y, va[mt][1].y, vb.x, vb.y);
            // step 1: (.z = p0, .w = p1)
            #pragma unroll
            for (int mt = 0; mt < 2; mt++)
                mma16816(acc[mt][nt], va[mt][0].z, va[mt][1].z,
                         va[mt][0].w, va[mt][1].w, vb.z, vb.w);
        }
        __syncthreads();
    }

    // ---- epilogue ----
    #pragma unroll
    for (int mt = 0; mt < 2; mt++) {
        const int r0 = m0 + wm + mt * 16 + lr;
        const int r1 = r0 + 8;
        #pragma unroll
        for (int nt = 0; nt < 8; nt++) {
            const int cbase = n0 + wn + nt * 8 + lk * 2;
            float2 bv = *(const float2*)(bias + cbase);
            float o0 = acc[mt][nt][0] + bv.x;
            float o1 = acc[mt][nt][1] + bv.y;
            float o2 = acc[mt][nt][2] + bv.x;
            float o3 = acc[mt][nt][3] + bv.y;
            if (HASRES) {
                float2 rv0 = *(const float2*)(res + (size_t)r0 * N + cbase);
                float2 rv1 = *(const float2*)(res + (size_t)r1 * N + cbase);
                o0 += rv0.x; o1 += rv0.y; o2 += rv1.x; o3 += rv1.y;
            }
            if (RELU) {     // relu output feeds next GEMM: write fp16
                __half2* hout = (__half2*)outv;
                hout[((size_t)r0 * N + cbase) >> 1] =
                    __floats2half2_rn(fmaxf(o0, 0.f), fmaxf(o1, 0.f));
                hout[((size_t)r1 * N + cbase) >> 1] =
                    __floats2half2_rn(fmaxf(o2, 0.f), fmaxf(o3, 0.f));
            } else {
                float* fout = (float*)outv;
                float2 s0 = {o0, o1}, s1 = {o2, o3};
                *(float2*)(fout + (size_t)r0 * N + cbase) = s0;
                *(float2*)(fout + (size_t)r1 * N + cbase) = s1;
            }
        }
    }
    #undef LOAD_STAGE
}

// ---------------- windowed attention, 4 heads per block (fp16 output) -----------
#define AKSTR 129
#define ATTN_SMEM ((16*128 + 64*AKSTR + 4*16*64) * 4)   /* 57600 B */
__global__ void __launch_bounds__(128) attn_kernel(const float* __restrict__ qkv,
                                                   __half* __restrict__ aout)
{
    extern __shared__ float sm[];
    float* sQ = sm;                       // [16][128]
    float* sK = sm + 16 * 128;            // [64][AKSTR]
    float* sP = sK + 64 * AKSTR;          // [4][16][64]
    int w = blockIdx.x, b = blockIdx.y, z = blockIdx.z;
    int tid = threadIdx.x;
    size_t base = ((size_t)b * TEXT + (size_t)w * CHK) * 768;
    const int colq = z * 128;

    for (int idx = tid; idx < 16 * 128; idx += 128) {
        int r = idx >> 7, c = idx & 127;
        sQ[idx] = qkv[base + (size_t)(CTX + r) * 768 + colq + c];
    }
    for (int idx = tid; idx < 64 * 128; idx += 128) {
        int j = idx >> 7, c = idx & 127;
        sK[j * AKSTR + c] = qkv[base + (size_t)j * 768 + 256 + colq + c];
    }
    __syncthreads();

    int hl = tid >> 5, lane = tid & 31;
    const float scale = 0.17677669529663687f;  // 1/sqrt(32)
    for (int r = 0; r < CHK; r++) {
        float s0 = 0.f, s1 = 0.f;
        const float* qrow = sQ + r * 128 + hl * 32;
        const float* k0 = sK + lane * AKSTR + hl * 32;
        const float* k1 = sK + (lane + 32) * AKSTR + hl * 32;
        #pragma unroll
        for (int d = 0; d < DH; d++) {
            float q = qrow[d];
            s0 = fmaf(q, k0[d], s0);
            s1 = fmaf(q, k1[d], s1);
        }
        s0 *= scale; s1 *= scale;
        float mx = fmaxf(s0, s1);
        #pragma unroll
        for (int o = 16; o > 0; o >>= 1)
            mx = fmaxf(mx, __shfl_xor_sync(0xffffffffu, mx, o));
        float e0 = __expf(s0 - mx), e1 = __expf(s1 - mx);
        float sum = e0 + e1;
        #pragma unroll
        for (int o = 16; o > 0; o >>= 1)
            sum += __shfl_xor_sync(0xffffffffu, sum, o);
        float inv = __frcp_rn(sum);
        sP[(hl * CHK + r) * 64 + lane]      = e0 * inv;
        sP[(hl * CHK + r) * 64 + lane + 32] = e1 * inv;
    }
    float acc[CHK];
    #pragma unroll
    for (int r = 0; r < CHK; r++) acc[r] = 0.f;
    for (int j = 0; j < WL; j++) {
        float v = qkv[base + (size_t)j * 768 + 512 + colq + hl * 32 + lane];
        #pragma unroll
        for (int r = 0; r < CHK; r++)
            acc[r] = fmaf(sP[(hl * CHK + r) * 64 + j], v, acc[r]);
    }
    size_t obase = ((size_t)b * TT + (size_t)w * CHK) * CC + colq + hl * 32 + lane;
    #pragma unroll
    for (int r = 0; r < CHK; r++)
        aout[obase + (size_t)r * CC] = __float2half_rn(acc[r]);
}

// ---------------- layernorm; ROUND=1 also emits fp16 copy for next GEMM ---------
template<int ROUND>
__global__ void ln_kernel(const float* in, const float* __restrict__ g,
                          const float* __restrict__ bt, float* outp,
                          __half* outh)
{
    int row = blockIdx.x * 8 + (threadIdx.x >> 5);
    int lane = threadIdx.x & 31;
    const float* r = in + (size_t)row * CC;
    float v[8];
    float sum = 0.f;
    #pragma unroll
    for (int i = 0; i < 8; i++) { v[i] = r[lane + 32 * i]; sum += v[i]; }
    #pragma unroll
    for (int o = 16; o > 0; o >>= 1) sum += __shfl_xor_sync(0xffffffffu, sum, o);
    float mu = sum * (1.f / 256.f);
    float vs = 0.f;
    #pragma unroll
    for (int i = 0; i < 8; i++) { float d = v[i] - mu; vs = fmaf(d, d, vs); }
    #pragma unroll
    for (int o = 16; o > 0; o >>= 1) vs += __shfl_xor_sync(0xffffffffu, vs, o);
    float rs = rsqrtf(vs * (1.f / 256.f) + EPSL);
    float* o = outp + (size_t)row * CC;
    __half* oh = ROUND ? (outh + (size_t)row * CC) : (__half*)0;
    #pragma unroll
    for (int i = 0; i < 8; i++) {
        int c = lane + 32 * i;
        float y = (v[i] - mu) * rs * g[c] + bt[c];
        o[c] = y;
        if (ROUND) oh[c] = __float2half_rn(y);
    }
}

// ---------------- final transpose (B,T,C) -> (B,C,T) ----------------------------
__global__ void transpose_out(const float* __restrict__ act, float* __restrict__ out)
{
    __shared__ float tile[32][33];
    int b = blockIdx.z;
    int t0 = blockIdx.x * 32, c0 = blockIdx.y * 32;
    int tx = threadIdx.x & 31, ty = threadIdx.x >> 5;
    for (int i = ty; i < 32; i += 8)
        tile[i][tx] = act[((size_t)b * TT + t0 + i) * CC + c0 + tx];
    __syncthreads();
    for (int i = ty; i < 32; i += 8)
        out[((size_t)b * CC + c0 + i) * TT + t0 + tx] = tile[tx][i];
}

// ---------------- orchestration -------------------------------------------------
extern "C" void kernel_launch(void* const* d_in, const int* in_sizes, int n_in,
                              void* d_out, int out_size)
{
    (void)in_sizes; (void)n_in; (void)out_size;
    const float* x    = (const float*)d_in[0];
    const float* emb  = (const float*)d_in[1];
    const float* ctx  = (const float*)d_in[2];
    const float* Wqkv = (const float*)d_in[3];
    const float* bqkv = (const float*)d_in[4];
    const float* Wo   = (const float*)d_in[5];
    const float* bo   = (const float*)d_in[6];
    const float* W1   = (const float*)d_in[7];
    const float* b1   = (const float*)d_in[8];
    const float* W2   = (const float*)d_in[9];
    const float* b2   = (const float*)d_in[10];
    const float* ln1g = (const float*)d_in[11];
    const float* ln1b = (const float*)d_in[12];
    const float* ln3g = (const float*)d_in[13];
    const float* ln3b = (const float*)d_in[14];
    float* out     = (float*)d_out;
    float* out_ctx = out + (size_t)BB * CC * TT;

    float *actA, *actB, *qkv, *x1;
    __half *ext, *attn, *x1h, *h, *wts;
    cudaGetSymbolAddress((void**)&actA, g_actA);
    cudaGetSymbolAddress((void**)&actB, g_actB);
    cudaGetSymbolAddress((void**)&ext,  g_ext);
    cudaGetSymbolAddress((void**)&qkv,  g_qkv);
    cudaGetSymbolAddress((void**)&attn, g_attn);
    cudaGetSymbolAddress((void**)&x1,   g_x1);
    cudaGetSymbolAddress((void**)&x1h,  g_x1h);
    cudaGetSymbolAddress((void**)&h,    g_h);
    cudaGetSymbolAddress((void**)&wts,  g_wts);
    __half* wq = wts + WQ_OFF;
    __half* wo = wts + WO_OFF;
    __half* w1 = wts + W1_OFF;
    __half* w2 = wts + W2_OFF;

    cudaFuncSetAttribute(attn_kernel, cudaFuncAttributeMaxDynamicSharedMemorySize,
                         ATTN_SMEM);
    cudaFuncSetAttribute(mma_gemm<0,0>, cudaFuncAttributeMaxDynamicSharedMemorySize,
                         GEMM_SMEM);
    cudaFuncSetAttribute(mma_gemm<0,1>, cudaFuncAttributeMaxDynamicSharedMemorySize,
                         GEMM_SMEM);
    cudaFuncSetAttribute(mma_gemm<1,0>, cudaFuncAttributeMaxDynamicSharedMemorySize,
                         GEMM_SMEM);

    // weight conversion to fp16 (one launch)
    cvt_all_kernel<<<(int)(WTS_TOTAL / 256), 256>>>(Wqkv, Wo, W1, W2, wts);

    conv_kernel<<<dim3(CC, BB), 256>>>(x, emb, actA);

    float* cur = actA;
    float* nxt = actB;
    const int Mq = BB * TT;          // 16384
    const int Me = BB * TEXT;        // 17152
    for (int L = 0; L < NL; L++) {
        build_ext_snap<<<(BB * TEXT * CC) / 256, 256>>>(ctx, cur, ext, out_ctx, L);
        // fused QKV projection over extended tokens (fp16 tensor core, f32 out)
        mma_gemm<0, 0><<<dim3(768 / 128, Me / 128), 256, GEMM_SMEM>>>(
            ext, wq + (size_t)L * 768 * CC, bqkv + (size_t)L * 768,
            (const float*)0, qkv, Me, 768, CC);
        attn_kernel<<<dim3(WL, BB, 2), 128, ATTN_SMEM>>>(qkv, attn);
        // Wo + residual(cur f32) -> x1 f32, then LN1 (emits f32 + fp16)
        mma_gemm<0, 1><<<dim3(CC / 128, Mq / 128), 256, GEMM_SMEM>>>(
            attn, wo + (size_t)L * CC * CC, bo + (size_t)L * CC,
            cur, x1, Mq, CC, CC);
        ln_kernel<1><<<Mq / 8, 256>>>(x1, ln1g + (size_t)L * CC, ln1b + (size_t)L * CC,
                                      x1, x1h);
        // FF1 (relu, fp16 out)
        mma_gemm<1, 0><<<dim3(FFD / 128, Mq / 128), 256, GEMM_SMEM>>>(
            x1h, w1 + (size_t)L * FFD * CC, b1 + (size_t)L * FFD,
            (const float*)0, h, Mq, FFD, CC);
        // FF2 + residual(x1 f32) -> nxt f32, then LN3 (f32 only)
        mma_gemm<0, 1><<<dim3(CC / 128, Mq / 128), 256, GEMM_SMEM>>>(
            h, w2 + (size_t)L * CC * FFD, b2 + (size_t)L * CC,
            x1, nxt, Mq, CC, FFD);
        ln_kernel<0><<<Mq / 8, 256>>>(nxt, ln3g + (size_t)L * CC, ln3b + (size_t)L * CC,
                                      nxt, (__half*)0);
        float* tmp = cur; cur = nxt; nxt = tmp;
    }

    transpose_out<<<dim3(TT / 32, CC / 32, BB), 256>>>(cur, out);
}